// round 12
// baseline (speedup 1.0000x reference)
#include <cuda_runtime.h>

#define IMG_H 2048
#define IMG_W 2048

// 32 MB static scratch for the separable intermediate (allowed: __device__ globals)
__device__ float g_S[IMG_H * IMG_W];
__device__ float g_D[IMG_H * IMG_W];

__device__ __forceinline__ float4 f4add(float4 a, float4 b) {
    return make_float4(a.x+b.x, a.y+b.y, a.z+b.z, a.w+b.w);
}
__device__ __forceinline__ float4 f4sub(float4 a, float4 b) {
    return make_float4(a.x-b.x, a.y-b.y, a.z-b.z, a.w-b.w);
}
__device__ __forceinline__ float4 f4fma(float w, float4 a, float4 acc) {
    return make_float4(fmaf(w,a.x,acc.x), fmaf(w,a.y,acc.y),
                       fmaf(w,a.z,acc.z), fmaf(w,a.w,acc.w));
}

// ======================= Kernel 1: horizontal pass =======================
// thread -> 4 cols of one row. 3 LDG.128 in, S/D via sliding sums, 2 STG.128 out.
__global__ __launch_bounds__(128)
void hpass_kernel(const float* __restrict__ x) {
    const int t   = blockIdx.x * 128 + threadIdx.x;   // 0..511 (column group)
    const int row = blockIdx.y;
    const int gx0 = t * 4;
    const float* __restrict__ rp = x + (size_t)row * IMG_W;

    float f[12];  // cols gx0-4 .. gx0+7
    if (t > 0 && t < (IMG_W/4 - 1)) {
        float4 a = *reinterpret_cast<const float4*>(rp + gx0 - 4);
        float4 b = *reinterpret_cast<const float4*>(rp + gx0);
        float4 c = *reinterpret_cast<const float4*>(rp + gx0 + 4);
        f[0]=a.x; f[1]=a.y; f[2]=a.z;  f[3]=a.w;
        f[4]=b.x; f[5]=b.y; f[6]=b.z;  f[7]=b.w;
        f[8]=c.x; f[9]=c.y; f[10]=c.z; f[11]=c.w;
    } else {
        #pragma unroll
        for (int m = 0; m < 12; m++)
            f[m] = rp[min(max(gx0 - 4 + m, 0), IMG_W - 1)];
    }

    float S0 = f[1]+f[2]+f[3]+f[4]+f[5]+f[6]+f[7];
    float S1 = S0 - f[1] + f[8];
    float S2 = S1 - f[2] + f[9];
    float S3 = S2 - f[3] + f[10];
    float D0 = fmaf(-3.f,f[1], fmaf(-2.f,f[2], fmaf(2.f,f[6], fmaf(3.f,f[7], f[5]-f[3]))));
    float D1 = fmaf(3.f, f[1], fmaf(4.f, f[8],  D0 - S1));
    float D2 = fmaf(3.f, f[2], fmaf(4.f, f[9],  D1 - S2));
    float D3 = fmaf(3.f, f[3], fmaf(4.f, f[10], D2 - S3));

    const size_t o = (size_t)row * IMG_W + gx0;
    *reinterpret_cast<float4*>(g_S + o) = make_float4(S0, S1, S2, S3);
    *reinterpret_cast<float4*>(g_D + o) = make_float4(D0, D1, D2, D3);
}

// ======================= Kernel 2: vertical pass =======================
// thread -> 4 cols x 8 rows. Rolling sums; "leaving" row re-loaded (L1 hit),
// no register ring, no smem, no barriers.
constexpr int STRIP = 8;

__device__ __forceinline__ size_t rowoff_clamped(int g) {
    return (size_t)min(max(g, 0), IMG_H - 1) * IMG_W;
}

template <bool VFAST>
__device__ __forceinline__ void vpass_body(float* __restrict__ out, int gx0, int gy0) {
    const float inv196 = 1.0f / 196.0f;
    const float inv49  = 1.0f / 49.0f;

    float4 sS = make_float4(0,0,0,0), sY = sS, sD = sS;

    // ---- init: 7-tap over rows gy0-3 .. gy0+3 ----
    #pragma unroll
    for (int k = -3; k <= 3; k++) {
        const size_t ro = VFAST ? (size_t)(gy0 + k) * IMG_W : rowoff_clamped(gy0 + k);
        float4 Sk = *reinterpret_cast<const float4*>(g_S + ro + gx0);
        float4 Dk = *reinterpret_cast<const float4*>(g_D + ro + gx0);
        sS = f4add(sS, Sk);
        sY = f4fma((float)k, Sk, sY);
        sD = f4add(sD, Dk);
    }

    float* __restrict__ op = out + ((size_t)gy0 * IMG_W + gx0) * 3;

    #pragma unroll
    for (int r = 0; r < STRIP; r++) {
        // ---- store output row gy0+r ----
        float4 p0 = make_float4(sD.x*inv196, sY.x*inv196, sS.x*inv49, sD.y*inv196);
        float4 p1 = make_float4(sY.y*inv196, sS.y*inv49,  sD.z*inv196, sY.z*inv196);
        float4 p2 = make_float4(sS.z*inv49,  sD.w*inv196, sY.w*inv196, sS.w*inv49);
        __stcs(reinterpret_cast<float4*>(op) + 0, p0);
        __stcs(reinterpret_cast<float4*>(op) + 1, p1);
        __stcs(reinterpret_cast<float4*>(op) + 2, p2);
        op += (size_t)3 * IMG_W;

        if (r < STRIP - 1) {
            // ---- roll window: leave row g-3, enter row g+4 (g = gy0+r) ----
            const size_t rl = VFAST ? (size_t)(gy0 + r - 3) * IMG_W : rowoff_clamped(gy0 + r - 3);
            const size_t re = VFAST ? (size_t)(gy0 + r + 4) * IMG_W : rowoff_clamped(gy0 + r + 4);
            float4 Sl = *reinterpret_cast<const float4*>(g_S + rl + gx0);
            float4 Se = *reinterpret_cast<const float4*>(g_S + re + gx0);
            float4 Dl = *reinterpret_cast<const float4*>(g_D + rl + gx0);
            float4 De = *reinterpret_cast<const float4*>(g_D + re + gx0);
            // sY' = sY - sS + 4*S_leave + 3*S_enter  (uses OLD sS)
            sY = f4fma(4.f, Sl, f4fma(3.f, Se, f4sub(sY, sS)));
            sS = f4add(f4sub(sS, Sl), Se);
            sD = f4add(f4sub(sD, Dl), De);
        }
    }
}

__global__ __launch_bounds__(128)
void vpass_kernel(float* __restrict__ out) {
    const int gx0 = (blockIdx.x * 128 + threadIdx.x) * 4;
    const int gy0 = blockIdx.y * STRIP;
    // VFAST: all touched row indices gy0-3 .. gy0+STRIP-1+4 stay in range
    if (gy0 >= 3 && gy0 + STRIP + 3 <= IMG_H - 1) vpass_body<true >(out, gx0, gy0);
    else                                          vpass_body<false>(out, gx0, gy0);
}

extern "C" void kernel_launch(void* const* d_in, const int* in_sizes, int n_in,
                              void* d_out, int out_size) {
    const float* x = (const float*)d_in[0];
    float* out = (float*)d_out;

    dim3 b1(128), g1(IMG_W / (128 * 4), IMG_H);        // (4, 2048) = 8192 blocks
    hpass_kernel<<<g1, b1>>>(x);

    dim3 b2(128), g2(IMG_W / (128 * 4), IMG_H / STRIP); // (4, 256) = 1024 blocks
    vpass_kernel<<<g2, b2>>>(out);
}

// round 13
// speedup vs baseline: 1.3839x; 1.3839x over previous
#include <cuda_runtime.h>

#define IMG_H 2048
#define IMG_W 2048

constexpr int TW = 128;   // tile cols
constexpr int TH = 32;    // tile rows (output)
constexpr int SROWS = TH + 6;       // 38 staged input rows
constexpr int SCOLS = TW + 8;       // 136 staged cols (gx0-4 .. gx0+131)
constexpr int SSTRIDE = 140;        // floats; 560B row stride, 16B aligned

__device__ __forceinline__ float4 f4add(float4 a, float4 b) {
    return make_float4(a.x+b.x, a.y+b.y, a.z+b.z, a.w+b.w);
}
__device__ __forceinline__ float4 f4sub(float4 a, float4 b) {
    return make_float4(a.x-b.x, a.y-b.y, a.z-b.z, a.w-b.w);
}
__device__ __forceinline__ float4 f4fma(float w, float4 a, float4 acc) {
    return make_float4(fmaf(w,a.x,acc.x), fmaf(w,a.y,acc.y),
                       fmaf(w,a.z,acc.z), fmaf(w,a.w,acc.w));
}

// S/D for 4 columns from a staged smem row (window f0..f11 at float offset 4*tx)
__device__ __forceinline__ void sd_from_smem(const float* __restrict__ rowp,
                                             float4& S, float4& D) {
    const float4 a = *reinterpret_cast<const float4*>(rowp);      // f0..f3
    const float4 b = *reinterpret_cast<const float4*>(rowp + 4);  // f4..f7
    const float4 c = *reinterpret_cast<const float4*>(rowp + 8);  // f8..f11
    float S0 = a.y + a.z + a.w + b.x + b.y + b.z + b.w;
    float S1 = S0 - a.y + c.x;
    float S2 = S1 - a.z + c.y;
    float S3 = S2 - a.w + c.z;
    float D0 = fmaf(-3.f, a.y, fmaf(-2.f, a.z, fmaf(2.f, b.z, fmaf(3.f, b.w, b.y - a.w))));
    float D1 = fmaf(3.f, a.y, fmaf(4.f, c.x, D0 - S1));
    float D2 = fmaf(3.f, a.z, fmaf(4.f, c.y, D1 - S2));
    float D3 = fmaf(3.f, a.w, fmaf(4.f, c.z, D2 - S3));
    S = make_float4(S0, S1, S2, S3);
    D = make_float4(D0, D1, D2, D3);
}

__global__ __launch_bounds__(256)
void plane_fit_kernel(const float* __restrict__ x, float* __restrict__ out) {
    __shared__ __align__(16) float raw[SROWS][SSTRIDE];

    const int tx  = threadIdx.x;   // 0..31
    const int ty  = threadIdx.y;   // 0..7
    const int tid = ty * 32 + tx;
    const int bx0 = blockIdx.x * TW;
    const int gy0 = blockIdx.y * TH;

    // ================= Stage raw input tile: rows gy0-3..gy0+34, cols bx0-4..bx0+131
    const bool xint = (bx0 >= 4) && (bx0 + TW + 3 < IMG_W);   // interior in x
    if (xint) {
        // 38 rows x 34 float4
        #pragma unroll
        for (int i = tid; i < SROWS * 34; i += 256) {
            const int r  = i / 34;
            const int c4 = i % 34;
            const int gy = min(max(gy0 - 3 + r, 0), IMG_H - 1);
            const float4 v = *reinterpret_cast<const float4*>(
                x + (size_t)gy * IMG_W + (bx0 - 4) + 4 * c4);
            *reinterpret_cast<float4*>(&raw[r][4 * c4]) = v;
        }
    } else {
        #pragma unroll
        for (int i = tid; i < SROWS * SCOLS; i += 256) {
            const int r = i / SCOLS;
            const int c = i % SCOLS;
            const int gy = min(max(gy0 - 3 + r, 0), IMG_H - 1);
            const int gx = min(max(bx0 - 4 + c, 0), IMG_W - 1);
            raw[r][c] = x[(size_t)gy * IMG_W + gx];
        }
    }
    __syncthreads();

    // ================= Vertical: 4 cols x 4 rows per thread, all from smem
    const int r0  = ty * 4;            // first local output row
    const int gx0 = bx0 + 4 * tx;      // first owned global col
    const float inv196 = 1.0f / 196.0f;
    const float inv49  = 1.0f / 49.0f;

    float4 Sl[3], Dl[3];               // leaving rows r0, r0+1, r0+2
    float4 sS = make_float4(0,0,0,0), sY = sS, sD = sS;

    // init 7-tap over smem rows r0 .. r0+6
    #pragma unroll
    for (int j = 0; j < 7; j++) {
        float4 S, D;
        sd_from_smem(&raw[r0 + j][4 * tx], S, D);
        if (j < 3) { Sl[j] = S; Dl[j] = D; }
        const float w = (float)(j - 3);
        sS = f4add(sS, S);
        sY = f4fma(w, S, sY);
        sD = f4add(sD, D);
    }

    float* __restrict__ op = out + ((size_t)(gy0 + r0) * IMG_W + gx0) * 3;

    #pragma unroll
    for (int ri = 0; ri < 4; ri++) {
        // store output row gy0+r0+ri
        float4 p0 = make_float4(sD.x*inv196, sY.x*inv196, sS.x*inv49, sD.y*inv196);
        float4 p1 = make_float4(sY.y*inv196, sS.y*inv49,  sD.z*inv196, sY.z*inv196);
        float4 p2 = make_float4(sS.z*inv49,  sD.w*inv196, sY.w*inv196, sS.w*inv49);
        __stcs(reinterpret_cast<float4*>(op) + 0, p0);
        __stcs(reinterpret_cast<float4*>(op) + 1, p1);
        __stcs(reinterpret_cast<float4*>(op) + 2, p2);
        op += (size_t)3 * IMG_W;

        if (ri < 3) {
            // roll: leave row r0+ri, enter row r0+ri+7
            float4 Se, De;
            sd_from_smem(&raw[r0 + ri + 7][4 * tx], Se, De);
            const float4 Sv = Sl[ri], Dv = Dl[ri];
            // sY' = sY - sS + 4*S_leave + 3*S_enter   (uses OLD sS)
            sY = f4fma(4.f, Sv, f4fma(3.f, Se, f4sub(sY, sS)));
            sS = f4add(f4sub(sS, Sv), Se);
            sD = f4add(f4sub(sD, Dv), De);
        }
    }
}

extern "C" void kernel_launch(void* const* d_in, const int* in_sizes, int n_in,
                              void* d_out, int out_size) {
    const float* x = (const float*)d_in[0];
    float* out = (float*)d_out;
    dim3 block(32, 8);
    dim3 grid(IMG_W / TW, IMG_H / TH);   // (16, 64) = 1024 blocks
    plane_fit_kernel<<<grid, block>>>(x, out);
}